// round 3
// baseline (speedup 1.0000x reference)
#include <cuda_runtime.h>
#include <cstdint>

#define FULL 0xFFFFFFFFu

// feat [b][k] (b-major, 32 x 2048). 256KB static scratch.
__device__ float g_feat[32 * 2048];
__device__ unsigned g_flag = 0;   // prep-done counter (self-resetting)
__device__ unsigned g_done = 0;   // block-done counter (self-resetting)

static const int NBLK = 288;      // 32 prep + 256 gemm

// Order-preserving float <-> uint mapping.
__device__ __forceinline__ unsigned f2ord(float f) {
    unsigned b = __float_as_uint(f);
    return (b & 0x80000000u) ? ~b : (b | 0x80000000u);
}
__device__ __forceinline__ float ord2f(unsigned u) {
    unsigned b = (u & 0x80000000u) ? (u ^ 0x80000000u) : ~u;
    return __uint_as_float(b);
}

// Packed fp32x2 FMA: d.xy = a.xy * b.xy + c.xy  (Blackwell FFMA2)
__device__ __forceinline__ unsigned long long ffma2(
    unsigned long long a, unsigned long long b, unsigned long long c) {
    unsigned long long d;
    asm("fma.rn.f32x2 %0, %1, %2, %3;" : "=l"(d) : "l"(a), "l"(b), "l"(c));
    return d;
}

__global__ void __launch_bounds__(256) fused_kernel(
    const float* __restrict__ f_rad,    // [32,1024]
    const float* __restrict__ f_histo,  // [32,2048]
    const int*   __restrict__ rad_mask, // [32]
    const int*   __restrict__ histo_mask,
    const float* __restrict__ W,        // [1024,2048]
    const float* __restrict__ bias,     // [1024]
    const float* __restrict__ token,    // [1024]
    float* __restrict__ out)            // [32,1024]
{
    // shared: gemm tiles + prep scratch (sum < 48KB static limit)
    __shared__ __align__(16) float Ws[128 * 64];   // [c][k] 32KB
    __shared__ __align__(16) float Fs[32 * 68];    // [b][k] pitch 68 (8.7KB)
    __shared__ float    s_red[16];
    __shared__ unsigned s_candT[64];
    __shared__ unsigned s_candB[64];
    __shared__ float    s_scal[4];

    const int tid  = threadIdx.x;
    const int lane = tid & 31;
    const int wid  = tid >> 5;

    if (blockIdx.x < 32) {
        // ================= PREP (one block per batch) =================
        const int b = blockIdx.x;
        float flag = ((rad_mask[b] != 0) && (histo_mask[b] != 0)) ? 0.f : 1.f;
        for (int c = tid; c < 1024; c += 256)
            out[b * 1024 + c] = bias[c] + flag * token[c];

        const float* rad = f_rad   + b * 1024;
        const float* his = f_histo + b * 2048;

        // norms
        float sr = 0.f, sh = 0.f;
        #pragma unroll
        for (int j = 0; j < 4; j++) { float v = rad[tid + 256 * j]; sr += v * v; }
        #pragma unroll
        for (int j = 0; j < 8; j++) { float v = his[tid + 256 * j]; sh += v * v; }
        #pragma unroll
        for (int o = 16; o > 0; o >>= 1) {
            sr += __shfl_xor_sync(FULL, sr, o);
            sh += __shfl_xor_sync(FULL, sh, o);
        }
        if (lane == 0) { s_red[wid] = sr; s_red[8 + wid] = sh; }
        __syncthreads();
        if (tid == 0) {
            float a = 0.f, c2 = 0.f;
            #pragma unroll
            for (int w = 0; w < 8; w++) { a += s_red[w]; c2 += s_red[8 + w]; }
            s_scal[0] = 1.f / fmaxf(sqrtf(a),  1e-12f);
            s_scal[1] = 1.f / fmaxf(sqrtf(c2), 1e-12f);
        }

        // selection: warps 0-3 top-16 of 512-elem slices, warps 4-7 bottom-16
        unsigned v[16];
        {
            const int base = (wid & 3) * 512;
            #pragma unroll
            for (int j = 0; j < 16; j++)
                v[j] = f2ord(his[base + j * 32 + lane]);
        }
        if (wid < 4) {
            #pragma unroll 1
            for (int p = 0; p < 16; p++) {
                unsigned lm = 0u;
                #pragma unroll
                for (int j = 0; j < 16; j++) lm = max(lm, v[j]);
                unsigned wm   = __reduce_max_sync(FULL, lm);
                unsigned ball = __ballot_sync(FULL, lm == wm);
                if (lane == __ffs(ball) - 1) {
                    bool d = false;
                    #pragma unroll
                    for (int j = 0; j < 16; j++)
                        if (!d && v[j] == wm) { v[j] = 0u; d = true; }
                }
                if (lane == 0) s_candT[(wid & 3) * 16 + p] = wm;
            }
        } else {
            #pragma unroll 1
            for (int p = 0; p < 16; p++) {
                unsigned lm = 0xFFFFFFFFu;
                #pragma unroll
                for (int j = 0; j < 16; j++) lm = min(lm, v[j]);
                unsigned wm   = __reduce_min_sync(FULL, lm);
                unsigned ball = __ballot_sync(FULL, lm == wm);
                if (lane == __ffs(ball) - 1) {
                    bool d = false;
                    #pragma unroll
                    for (int j = 0; j < 16; j++)
                        if (!d && v[j] == wm) { v[j] = 0xFFFFFFFFu; d = true; }
                }
                if (lane == 0) s_candB[(wid - 4) * 16 + p] = wm;
            }
        }
        __syncthreads();

        if (wid == 0) {
            unsigned a0 = s_candT[lane], a1 = s_candT[32 + lane];
            float ssum = 0.f;
            #pragma unroll 1
            for (int p = 0; p < 16; p++) {
                unsigned lm = max(a0, a1);
                unsigned wm = __reduce_max_sync(FULL, lm);
                ssum += ord2f(wm);
                unsigned ball = __ballot_sync(FULL, lm == wm);
                if (lane == __ffs(ball) - 1) { if (a0 == wm) a0 = 0u; else a1 = 0u; }
            }
            if (lane == 0) s_scal[2] = ssum;
        } else if (wid == 1) {
            unsigned a0 = s_candB[lane], a1 = s_candB[32 + lane];
            float ssum = 0.f;
            #pragma unroll 1
            for (int p = 0; p < 16; p++) {
                unsigned lm = min(a0, a1);
                unsigned wm = __reduce_min_sync(FULL, lm);
                ssum += ord2f(wm);
                unsigned ball = __ballot_sync(FULL, lm == wm);
                if (lane == __ffs(ball) - 1) { if (a0 == wm) a0 = 0xFFFFFFFFu; else a1 = 0xFFFFFFFFu; }
            }
            if (lane == 0) s_scal[3] = ssum;
        }
        __syncthreads();

        const float inv_r = s_scal[0];
        const float Tp = s_scal[1] * s_scal[2] * (1.f / 16.f);
        const float Tn = s_scal[1] * s_scal[3] * (1.f / 16.f);

        for (int i = tid; i < 1024; i += 256) {
            float r = rad[i] * inv_r;
            float p = fmaxf(r, 0.f), m = fminf(r, 0.f);
            g_feat[b * 2048 + i]        =  Tp * p + Tn * m;
            g_feat[b * 2048 + 1024 + i] = -(Tn * p + Tp * m);
        }

        __syncthreads();
        if (tid == 0) {
            __threadfence();
            atomicAdd(&g_flag, 1u);   // signal this batch's data is ready
        }
    } else {
        // ================= GEMM: out[b,c] += sum_k feat[b][k] * W[c][k] =================
        const int gb = blockIdx.x - 32;
        const int c0 = (gb & 7) * 128;        // 8 c-tiles of 128
        const int k0 = (gb >> 3) * 64;        // 32 k-splits of 64

        // --- issue W loads FIRST (overlaps DRAM latency with prep wait) ---
        const float4* W4 = (const float4*)W;
        const int cb = tid >> 4;              // 0..15
        const int kq = tid & 15;              // 0..15
        const int kq0 = k0 >> 2;
        float4 v[8];
        #pragma unroll
        for (int j = 0; j < 8; j++)
            v[j] = W4[(size_t)(c0 + cb + 16 * j) * 512 + kq0 + kq];

        // --- wait for prep ---
        if (tid == 0) {
            volatile unsigned* fl = &g_flag;
            while (*fl < 32u) { __nanosleep(64); }
        }
        __syncthreads();
        __threadfence();

        // --- store W tile to smem [c][k] (straight copy, coalesced) ---
        float4* Ws4 = (float4*)Ws;
        #pragma unroll
        for (int j = 0; j < 8; j++)
            Ws4[(cb + 16 * j) * 16 + kq] = v[j];

        // --- stage feat chunk [32][64] with pitch 68 ---
        {
            int idx = tid;
            #pragma unroll
            for (int rep = 0; rep < 2; rep++) {
                int bb  = idx >> 4;
                int kq2 = idx & 15;
                float4 f = *(const float4*)&g_feat[bb * 2048 + k0 + 4 * kq2];
                *(float4*)&Fs[bb * 68 + 4 * kq2] = f;
                idx += 256;
            }
        }
        __syncthreads();

        // --- compute: lane = b, warp owns 16 c rows ---
        const int cw = wid * 16;             // warp's c offset in tile
        const ulonglong2* wrow = (const ulonglong2*)&Ws[cw * 64];   // row = 16 ull2
        const ulonglong2* frow = (const ulonglong2*)&Fs[lane * 68]; // own b row

        unsigned long long acc[16];
        #pragma unroll
        for (int c = 0; c < 16; c++) acc[c] = 0ull;

        #pragma unroll
        for (int ki = 0; ki < 16; ki++) {          // 16 iters x 4 k
            ulonglong2 f = frow[ki];               // 2 f32x2 k-pairs (per-lane)
            #pragma unroll
            for (int c = 0; c < 16; c++) {
                ulonglong2 wv = wrow[c * 16 + ki]; // uniform broadcast LDS.128
                acc[c] = ffma2(wv.x, f.x, acc[c]);
                acc[c] = ffma2(wv.y, f.y, acc[c]);
            }
        }

        // --- tail: fold f32x2 halves, accumulate into out ---
        float* o = out + lane * 1024 + c0 + cw;
        #pragma unroll
        for (int c = 0; c < 16; c++) {
            float lo = __uint_as_float((unsigned)(acc[c] & 0xffffffffull));
            float hi = __uint_as_float((unsigned)(acc[c] >> 32));
            atomicAdd(o + c, lo + hi);
        }
        __syncthreads();
    }

    // ---- epilogue: last block resets flags so graph replays start clean ----
    if (tid == 0) {
        __threadfence();
        unsigned d = atomicAdd(&g_done, 1u);
        if (d == (unsigned)(NBLK - 1)) {
            g_done = 0u;
            g_flag = 0u;
            __threadfence();
        }
    }
}

extern "C" void kernel_launch(void* const* d_in, const int* in_sizes, int n_in,
                              void* d_out, int out_size) {
    const float* f_rad      = (const float*)d_in[0];
    const float* f_histo    = (const float*)d_in[1];
    const int*   rad_mask   = (const int*)  d_in[2];
    const int*   histo_mask = (const int*)  d_in[3];
    const float* W          = (const float*)d_in[4];
    const float* bias       = (const float*)d_in[5];
    const float* token      = (const float*)d_in[6];
    float* out = (float*)d_out;

    fused_kernel<<<NBLK, 256>>>(f_rad, f_histo, rad_mask, histo_mask, W, bias, token, out);
}

// round 4
// speedup vs baseline: 1.2083x; 1.2083x over previous
#include <cuda_runtime.h>
#include <cstdint>

#define FULL 0xFFFFFFFFu

// feat [b][k] (b-major, 32 x 2048). 256KB static scratch.
__device__ float g_feat[32 * 2048];

// Order-preserving float <-> uint mapping.
__device__ __forceinline__ unsigned f2ord(float f) {
    unsigned b = __float_as_uint(f);
    return (b & 0x80000000u) ? ~b : (b | 0x80000000u);
}
__device__ __forceinline__ float ord2f(unsigned u) {
    unsigned b = (u & 0x80000000u) ? (u ^ 0x80000000u) : ~u;
    return __uint_as_float(b);
}

// Packed fp32x2 FMA (Blackwell FFMA2): d = a*b + c elementwise on 2 floats.
__device__ __forceinline__ unsigned long long ffma2(
    unsigned long long a, unsigned long long b, unsigned long long c) {
    unsigned long long d;
    asm("fma.rn.f32x2 %0, %1, %2, %3;" : "=l"(d) : "l"(a), "l"(b), "l"(c));
    return d;
}

// ---------------------------------------------------------------------------
// Kernel A: per-batch prep. grid = 32, 256 threads.
// ---------------------------------------------------------------------------
__global__ void __launch_bounds__(256) prep_kernel(
    const float* __restrict__ f_rad,    // [32,1024]
    const float* __restrict__ f_histo,  // [32,2048]
    const int*   __restrict__ rad_mask, // [32]
    const int*   __restrict__ histo_mask,
    const float* __restrict__ bias,     // [1024]
    const float* __restrict__ token,    // [1024]
    float* __restrict__ out)            // [32,1024]
{
    const int b    = blockIdx.x;
    const int tid  = threadIdx.x;
    const int lane = tid & 31;
    const int wid  = tid >> 5;

    __shared__ float    s_red[16];
    __shared__ unsigned s_candT[64];
    __shared__ unsigned s_candB[64];
    __shared__ float    s_scal[4];

    float flag = ((rad_mask[b] != 0) && (histo_mask[b] != 0)) ? 0.f : 1.f;
    for (int c = tid; c < 1024; c += 256)
        out[b * 1024 + c] = bias[c] + flag * token[c];

    const float* rad = f_rad   + b * 1024;
    const float* his = f_histo + b * 2048;

    // norms
    float sr = 0.f, sh = 0.f;
    #pragma unroll
    for (int j = 0; j < 4; j++) { float v = rad[tid + 256 * j]; sr += v * v; }
    #pragma unroll
    for (int j = 0; j < 8; j++) { float v = his[tid + 256 * j]; sh += v * v; }
    #pragma unroll
    for (int o = 16; o > 0; o >>= 1) {
        sr += __shfl_xor_sync(FULL, sr, o);
        sh += __shfl_xor_sync(FULL, sh, o);
    }
    if (lane == 0) { s_red[wid] = sr; s_red[8 + wid] = sh; }
    __syncthreads();
    if (tid == 0) {
        float a = 0.f, c2 = 0.f;
        #pragma unroll
        for (int w = 0; w < 8; w++) { a += s_red[w]; c2 += s_red[8 + w]; }
        s_scal[0] = 1.f / fmaxf(sqrtf(a),  1e-12f);
        s_scal[1] = 1.f / fmaxf(sqrtf(c2), 1e-12f);
    }

    // selection: warps 0-3 top-16 of 512-elem slices, warps 4-7 bottom-16
    unsigned v[16];
    {
        const int base = (wid & 3) * 512;
        #pragma unroll
        for (int j = 0; j < 16; j++)
            v[j] = f2ord(his[base + j * 32 + lane]);
    }
    if (wid < 4) {
        #pragma unroll 1
        for (int p = 0; p < 16; p++) {
            unsigned lm = 0u;
            #pragma unroll
            for (int j = 0; j < 16; j++) lm = max(lm, v[j]);
            unsigned wm   = __reduce_max_sync(FULL, lm);
            unsigned ball = __ballot_sync(FULL, lm == wm);
            if (lane == __ffs(ball) - 1) {
                bool d = false;
                #pragma unroll
                for (int j = 0; j < 16; j++)
                    if (!d && v[j] == wm) { v[j] = 0u; d = true; }
            }
            if (lane == 0) s_candT[(wid & 3) * 16 + p] = wm;
        }
    } else {
        #pragma unroll 1
        for (int p = 0; p < 16; p++) {
            unsigned lm = 0xFFFFFFFFu;
            #pragma unroll
            for (int j = 0; j < 16; j++) lm = min(lm, v[j]);
            unsigned wm   = __reduce_min_sync(FULL, lm);
            unsigned ball = __ballot_sync(FULL, lm == wm);
            if (lane == __ffs(ball) - 1) {
                bool d = false;
                #pragma unroll
                for (int j = 0; j < 16; j++)
                    if (!d && v[j] == wm) { v[j] = 0xFFFFFFFFu; d = true; }
            }
            if (lane == 0) s_candB[(wid - 4) * 16 + p] = wm;
        }
    }
    __syncthreads();

    if (wid == 0) {
        unsigned a0 = s_candT[lane], a1 = s_candT[32 + lane];
        float ssum = 0.f;
        #pragma unroll 1
        for (int p = 0; p < 16; p++) {
            unsigned lm = max(a0, a1);
            unsigned wm = __reduce_max_sync(FULL, lm);
            ssum += ord2f(wm);
            unsigned ball = __ballot_sync(FULL, lm == wm);
            if (lane == __ffs(ball) - 1) { if (a0 == wm) a0 = 0u; else a1 = 0u; }
        }
        if (lane == 0) s_scal[2] = ssum;
    } else if (wid == 1) {
        unsigned a0 = s_candB[lane], a1 = s_candB[32 + lane];
        float ssum = 0.f;
        #pragma unroll 1
        for (int p = 0; p < 16; p++) {
            unsigned lm = min(a0, a1);
            unsigned wm = __reduce_min_sync(FULL, lm);
            ssum += ord2f(wm);
            unsigned ball = __ballot_sync(FULL, lm == wm);
            if (lane == __ffs(ball) - 1) { if (a0 == wm) a0 = 0xFFFFFFFFu; else a1 = 0xFFFFFFFFu; }
        }
        if (lane == 0) s_scal[3] = ssum;
    }
    __syncthreads();

    const float inv_r = s_scal[0];
    const float Tp = s_scal[1] * s_scal[2] * (1.f / 16.f);
    const float Tn = s_scal[1] * s_scal[3] * (1.f / 16.f);

    for (int i = tid; i < 1024; i += 256) {
        float r = rad[i] * inv_r;
        float p = fmaxf(r, 0.f), m = fminf(r, 0.f);
        g_feat[b * 2048 + i]        =  Tp * p + Tn * m;
        g_feat[b * 2048 + 1024 + i] = -(Tn * p + Tp * m);
    }
}

// ---------------------------------------------------------------------------
// Kernel B: skinny GEMM  out[b,c] += sum_k feat[b][k] * W[c][k]
// grid = (16 c-tiles of 64, 32 k-splits of 64), 256 threads.
// 512 blocks -> ~28 warps/SM. Batched 6x LDG.128 prefetch per thread.
// Microkernel: warp = 8 c-rows, lane = b; FFMA2 along k.
// ---------------------------------------------------------------------------
__global__ void __launch_bounds__(256) gemm_kernel(
    const float* __restrict__ W,   // [1024, 2048] row-major
    float* __restrict__ out)       // [32, 1024]
{
    const int c0  = blockIdx.x * 64;
    const int k0  = blockIdx.y * 64;
    const int tid = threadIdx.x;
    const int lane = tid & 31;
    const int wid  = tid >> 5;

    __shared__ __align__(16) float Ws[64 * 64];   // [c][k] 16KB
    __shared__ __align__(16) float Fs[32 * 68];   // [b][k] pitch 68 (8.7KB)

    // ---- batched prefetch: 4x W + 2x feat LDG.128, all issued before any STS
    const float4* W4 = (const float4*)W;
    const int kq = tid & 15;              // float4 index along k (0..15)
    const int cl = tid >> 4;              // 0..15
    const int kq0 = k0 >> 2;
    float4 wv[4];
    #pragma unroll
    for (int j = 0; j < 4; j++)           // c rows cl, cl+16, cl+32, cl+48
        wv[j] = W4[(size_t)(c0 + cl + 16 * j) * 512 + kq0 + kq];
    float4 fv[2];
    {
        const float4* F4l = (const float4*)g_feat;
        // i = tid + 256*j, i in [0,512): bb = i>>4, kq2 = i&15
        #pragma unroll
        for (int j = 0; j < 2; j++) {
            int i = tid + 256 * j;
            fv[j] = F4l[(size_t)(i >> 4) * 512 + kq0 + (i & 15)];
        }
    }

    // ---- stores to smem
    #pragma unroll
    for (int j = 0; j < 4; j++)
        *(float4*)&Ws[(cl + 16 * j) * 64 + 4 * kq] = wv[j];
    #pragma unroll
    for (int j = 0; j < 2; j++) {
        int i = tid + 256 * j;
        *(float4*)&Fs[(i >> 4) * 68 + 4 * (i & 15)] = fv[j];
    }
    __syncthreads();

    // ---- compute: warp owns 8 c rows (cw..cw+7), lane = b
    const int cw = wid * 8;
    const ulonglong2* wrow = (const ulonglong2*)&Ws[cw * 64];   // 16 ull2 per c-row
    const ulonglong2* frow = (const ulonglong2*)&Fs[lane * 68]; // own b row

    unsigned long long acc[8];
    #pragma unroll
    for (int c = 0; c < 8; c++) acc[c] = 0ull;

    #pragma unroll
    for (int ki = 0; ki < 16; ki++) {          // 16 iters x 4 k
        ulonglong2 f = frow[ki];               // per-lane, conflict-free
        #pragma unroll
        for (int c = 0; c < 8; c++) {
            ulonglong2 w = wrow[c * 16 + ki];  // warp-uniform broadcast
            acc[c] = ffma2(w.x, f.x, acc[c]);
            acc[c] = ffma2(w.y, f.y, acc[c]);
        }
    }

    // ---- fold halves, accumulate
    float* o = out + lane * 1024 + c0 + cw;
    #pragma unroll
    for (int c = 0; c < 8; c++) {
        float lo = __uint_as_float((unsigned)(acc[c] & 0xffffffffull));
        float hi = __uint_as_float((unsigned)(acc[c] >> 32));
        atomicAdd(o + c, lo + hi);
    }
}

extern "C" void kernel_launch(void* const* d_in, const int* in_sizes, int n_in,
                              void* d_out, int out_size) {
    const float* f_rad      = (const float*)d_in[0];
    const float* f_histo    = (const float*)d_in[1];
    const int*   rad_mask   = (const int*)  d_in[2];
    const int*   histo_mask = (const int*)  d_in[3];
    const float* W          = (const float*)d_in[4];
    const float* bias       = (const float*)d_in[5];
    const float* token      = (const float*)d_in[6];
    float* out = (float*)d_out;

    prep_kernel<<<32, 256>>>(f_rad, f_histo, rad_mask, histo_mask, bias, token, out);
    gemm_kernel<<<dim3(16, 32), 256>>>(W, out);
}

// round 5
// speedup vs baseline: 1.2889x; 1.0667x over previous
#include <cuda_runtime.h>
#include <cstdint>

#define FULL 0xFFFFFFFFu

// Static scratch (no allocations):
__device__ float4 g_scal[32];             // per-b: {inv_r, Tp, Tn, flag}
__device__ float  g_part[32 * 32 * 1024]; // [split][b][c] partials, 4MB

// Order-preserving float <-> uint mapping.
__device__ __forceinline__ unsigned f2ord(float f) {
    unsigned b = __float_as_uint(f);
    return (b & 0x80000000u) ? ~b : (b | 0x80000000u);
}
__device__ __forceinline__ float ord2f(unsigned u) {
    unsigned b = (u & 0x80000000u) ? (u ^ 0x80000000u) : ~u;
    return __uint_as_float(b);
}

// Packed fp32x2 FMA (Blackwell FFMA2).
__device__ __forceinline__ unsigned long long ffma2(
    unsigned long long a, unsigned long long b, unsigned long long c) {
    unsigned long long d;
    asm("fma.rn.f32x2 %0, %1, %2, %3;" : "=l"(d) : "l"(a), "l"(b), "l"(c));
    return d;
}

// ---------------------------------------------------------------------------
// Kernel A: per-batch prep -> 4 scalars per batch. grid = 32, 256 threads.
// ---------------------------------------------------------------------------
__global__ void __launch_bounds__(256) prep_kernel(
    const float* __restrict__ f_rad,    // [32,1024]
    const float* __restrict__ f_histo,  // [32,2048]
    const int*   __restrict__ rad_mask, // [32]
    const int*   __restrict__ histo_mask)
{
    const int b    = blockIdx.x;
    const int tid  = threadIdx.x;
    const int lane = tid & 31;
    const int wid  = tid >> 5;

    __shared__ float    s_red[16];
    __shared__ unsigned s_candT[64];
    __shared__ unsigned s_candB[64];
    __shared__ float    s_scal[4];

    const float* rad = f_rad   + b * 1024;
    const float* his = f_histo + b * 2048;

    // norms
    float sr = 0.f, sh = 0.f;
    #pragma unroll
    for (int j = 0; j < 4; j++) { float v = rad[tid + 256 * j]; sr += v * v; }
    #pragma unroll
    for (int j = 0; j < 8; j++) { float v = his[tid + 256 * j]; sh += v * v; }
    #pragma unroll
    for (int o = 16; o > 0; o >>= 1) {
        sr += __shfl_xor_sync(FULL, sr, o);
        sh += __shfl_xor_sync(FULL, sh, o);
    }
    if (lane == 0) { s_red[wid] = sr; s_red[8 + wid] = sh; }
    __syncthreads();
    if (tid == 0) {
        float a = 0.f, c2 = 0.f;
        #pragma unroll
        for (int w = 0; w < 8; w++) { a += s_red[w]; c2 += s_red[8 + w]; }
        s_scal[0] = 1.f / fmaxf(sqrtf(a),  1e-12f);
        s_scal[1] = 1.f / fmaxf(sqrtf(c2), 1e-12f);
    }

    // selection: warps 0-3 top-16 of 512-elem slices, warps 4-7 bottom-16
    unsigned v[16];
    {
        const int base = (wid & 3) * 512;
        #pragma unroll
        for (int j = 0; j < 16; j++)
            v[j] = f2ord(his[base + j * 32 + lane]);
    }
    if (wid < 4) {
        #pragma unroll 1
        for (int p = 0; p < 16; p++) {
            unsigned lm = 0u;
            #pragma unroll
            for (int j = 0; j < 16; j++) lm = max(lm, v[j]);
            unsigned wm   = __reduce_max_sync(FULL, lm);
            unsigned ball = __ballot_sync(FULL, lm == wm);
            if (lane == __ffs(ball) - 1) {
                bool d = false;
                #pragma unroll
                for (int j = 0; j < 16; j++)
                    if (!d && v[j] == wm) { v[j] = 0u; d = true; }
            }
            if (lane == 0) s_candT[(wid & 3) * 16 + p] = wm;
        }
    } else {
        #pragma unroll 1
        for (int p = 0; p < 16; p++) {
            unsigned lm = 0xFFFFFFFFu;
            #pragma unroll
            for (int j = 0; j < 16; j++) lm = min(lm, v[j]);
            unsigned wm   = __reduce_min_sync(FULL, lm);
            unsigned ball = __ballot_sync(FULL, lm == wm);
            if (lane == __ffs(ball) - 1) {
                bool d = false;
                #pragma unroll
                for (int j = 0; j < 16; j++)
                    if (!d && v[j] == wm) { v[j] = 0xFFFFFFFFu; d = true; }
            }
            if (lane == 0) s_candB[(wid - 4) * 16 + p] = wm;
        }
    }
    __syncthreads();

    if (wid == 0) {
        unsigned a0 = s_candT[lane], a1 = s_candT[32 + lane];
        float ssum = 0.f;
        #pragma unroll 1
        for (int p = 0; p < 16; p++) {
            unsigned lm = max(a0, a1);
            unsigned wm = __reduce_max_sync(FULL, lm);
            ssum += ord2f(wm);
            unsigned ball = __ballot_sync(FULL, lm == wm);
            if (lane == __ffs(ball) - 1) { if (a0 == wm) a0 = 0u; else a1 = 0u; }
        }
        if (lane == 0) s_scal[2] = ssum;
    } else if (wid == 1) {
        unsigned a0 = s_candB[lane], a1 = s_candB[32 + lane];
        float ssum = 0.f;
        #pragma unroll 1
        for (int p = 0; p < 16; p++) {
            unsigned lm = min(a0, a1);
            unsigned wm = __reduce_min_sync(FULL, lm);
            ssum += ord2f(wm);
            unsigned ball = __ballot_sync(FULL, lm == wm);
            if (lane == __ffs(ball) - 1) { if (a0 == wm) a0 = 0xFFFFFFFFu; else a1 = 0xFFFFFFFFu; }
        }
        if (lane == 0) s_scal[3] = ssum;
    }
    __syncthreads();

    if (tid == 0) {
        float flag = ((rad_mask[b] != 0) && (histo_mask[b] != 0)) ? 0.f : 1.f;
        float inv_r = s_scal[0];
        float Tp = s_scal[1] * s_scal[2] * (1.f / 16.f);
        float Tn = s_scal[1] * s_scal[3] * (1.f / 16.f);
        g_scal[b] = make_float4(inv_r, Tp, Tn, flag);
    }
}

// ---------------------------------------------------------------------------
// Kernel B: split-K GEMM, atomic-free.
//   part[split][b][c] = sum_{k in split} feat[b][k] * W[c][k]
// feat computed on the fly from f_rad + scalars.
// grid = (16 c-tiles of 64, 32 k-splits of 64), 256 threads.
// ---------------------------------------------------------------------------
__global__ void __launch_bounds__(256) gemm_kernel(
    const float* __restrict__ W,      // [1024, 2048]
    const float* __restrict__ f_rad)  // [32, 1024]
{
    const int c0    = blockIdx.x * 64;
    const int split = blockIdx.y;
    const int k0    = split * 64;
    const int tid   = threadIdx.x;
    const int lane  = tid & 31;
    const int wid   = tid >> 5;

    __shared__ __align__(16) float  Ws[64 * 64];   // [c][k] 16KB
    __shared__ __align__(16) float  Fs[32 * 68];   // [b][k] pitch 68
    __shared__ float4 s_sc[32];

    // ---- batched prefetch: 4x W LDG.128 + 2x rad LDG.128 + scalars
    const float4* W4 = (const float4*)W;
    const int kq  = tid & 15;
    const int cl  = tid >> 4;
    const int kq0 = k0 >> 2;
    float4 wv[4];
    #pragma unroll
    for (int j = 0; j < 4; j++)
        wv[j] = W4[(size_t)(c0 + cl + 16 * j) * 512 + kq0 + kq];

    const float4* R4 = (const float4*)f_rad;
    const int kb = (k0 & 1023) >> 2;   // float4 col base within rad row
    float4 rv[2];
    #pragma unroll
    for (int j = 0; j < 2; j++) {
        int i = tid + 256 * j;
        rv[j] = R4[(size_t)(i >> 4) * 256 + kb + (i & 15)];
    }
    if (tid < 32) s_sc[tid] = g_scal[tid];
    __syncthreads();   // s_sc visible

    // ---- feat on the fly: feat = ca*max(rad,0) + cb*min(rad,0)
    const bool neg = (k0 >= 1024);
    #pragma unroll
    for (int j = 0; j < 2; j++) {
        int i  = tid + 256 * j;
        int bb = i >> 4;
        float4 sc = s_sc[bb];
        float ca = (neg ? -sc.z : sc.y) * sc.x;
        float cb = (neg ? -sc.y : sc.z) * sc.x;
        float4 r = rv[j], f;
        f.x = ca * fmaxf(r.x, 0.f) + cb * fminf(r.x, 0.f);
        f.y = ca * fmaxf(r.y, 0.f) + cb * fminf(r.y, 0.f);
        f.z = ca * fmaxf(r.z, 0.f) + cb * fminf(r.z, 0.f);
        f.w = ca * fmaxf(r.w, 0.f) + cb * fminf(r.w, 0.f);
        *(float4*)&Fs[bb * 68 + 4 * (i & 15)] = f;
    }
    #pragma unroll
    for (int j = 0; j < 4; j++)
        *(float4*)&Ws[(cl + 16 * j) * 64 + 4 * kq] = wv[j];
    __syncthreads();

    // ---- microkernel: warp owns 8 c rows, lane = b
    const int cw = wid * 8;
    const ulonglong2* wrow = (const ulonglong2*)&Ws[cw * 64];
    const ulonglong2* frow = (const ulonglong2*)&Fs[lane * 68];

    unsigned long long acc[8];
    #pragma unroll
    for (int c = 0; c < 8; c++) acc[c] = 0ull;

    #pragma unroll
    for (int ki = 0; ki < 16; ki++) {
        ulonglong2 f = frow[ki];
        #pragma unroll
        for (int c = 0; c < 8; c++) {
            ulonglong2 w = wrow[c * 16 + ki];
            acc[c] = ffma2(w.x, f.x, acc[c]);
            acc[c] = ffma2(w.y, f.y, acc[c]);
        }
    }

    // ---- fold + plain stores to partial buffer (no atomics)
    float o8[8];
    #pragma unroll
    for (int c = 0; c < 8; c++) {
        float lo = __uint_as_float((unsigned)(acc[c] & 0xffffffffull));
        float hi = __uint_as_float((unsigned)(acc[c] >> 32));
        o8[c] = lo + hi;
    }
    float* dst = &g_part[((size_t)split * 32 + lane) * 1024 + c0 + cw];
    *(float4*)(dst + 0) = make_float4(o8[0], o8[1], o8[2], o8[3]);
    *(float4*)(dst + 4) = make_float4(o8[4], o8[5], o8[6], o8[7]);
}

// ---------------------------------------------------------------------------
// Kernel C: reduce 32 split partials + bias + flag*token -> out.
// grid = 32 (b), 256 threads (c quads).
// ---------------------------------------------------------------------------
__device__ __forceinline__ float4 f4add(float4 a, float4 b) {
    return make_float4(a.x + b.x, a.y + b.y, a.z + b.z, a.w + b.w);
}

__global__ void __launch_bounds__(256) reduce_kernel(
    const float* __restrict__ bias,   // [1024]
    const float* __restrict__ token,  // [1024]
    float* __restrict__ out)          // [32,1024]
{
    const int b   = blockIdx.x;
    const int tid = threadIdx.x;

    const float4* P4 = (const float4*)g_part;
    const size_t base   = (size_t)b * 256 + tid;   // float4 index for split 0
    const size_t stride = 32 * 256;                // float4s between splits

    float4 a0 = make_float4(0, 0, 0, 0), a1 = a0, a2 = a0, a3 = a0;
    #pragma unroll
    for (int s = 0; s < 32; s += 4) {
        a0 = f4add(a0, P4[base + (size_t)(s + 0) * stride]);
        a1 = f4add(a1, P4[base + (size_t)(s + 1) * stride]);
        a2 = f4add(a2, P4[base + (size_t)(s + 2) * stride]);
        a3 = f4add(a3, P4[base + (size_t)(s + 3) * stride]);
    }
    float4 acc = f4add(f4add(a0, a1), f4add(a2, a3));

    const float flag = g_scal[b].w;
    float4 bs = ((const float4*)bias)[tid];
    float4 tk = ((const float4*)token)[tid];
    float4 o;
    o.x = acc.x + bs.x + flag * tk.x;
    o.y = acc.y + bs.y + flag * tk.y;
    o.z = acc.z + bs.z + flag * tk.z;
    o.w = acc.w + bs.w + flag * tk.w;
    ((float4*)out)[(size_t)b * 256 + tid] = o;
}

extern "C" void kernel_launch(void* const* d_in, const int* in_sizes, int n_in,
                              void* d_out, int out_size) {
    const float* f_rad      = (const float*)d_in[0];
    const float* f_histo    = (const float*)d_in[1];
    const int*   rad_mask   = (const int*)  d_in[2];
    const int*   histo_mask = (const int*)  d_in[3];
    const float* W          = (const float*)d_in[4];
    const float* bias       = (const float*)d_in[5];
    const float* token      = (const float*)d_in[6];
    float* out = (float*)d_out;

    prep_kernel<<<32, 256>>>(f_rad, f_histo, rad_mask, histo_mask);
    gemm_kernel<<<dim3(16, 32), 256>>>(W, f_rad);
    reduce_kernel<<<32, 256>>>(bias, token, out);
}

// round 6
// speedup vs baseline: 1.4056x; 1.0906x over previous
#include <cuda_runtime.h>
#include <cstdint>

#define FULL 0xFFFFFFFFu

// Static scratch (no allocations):
__device__ float4 g_scal[32];             // per-b: {inv_r, Tp, Tn, flag}
__device__ float  g_part[32 * 32 * 1024]; // [split][b][c] partials, 4MB

// Order-preserving float <-> uint mapping (monotone for non-NaN).
__device__ __forceinline__ unsigned f2ord(float f) {
    unsigned b = __float_as_uint(f);
    return (b & 0x80000000u) ? ~b : (b | 0x80000000u);
}
__device__ __forceinline__ float ord2f(unsigned u) {
    unsigned b = (u & 0x80000000u) ? (u ^ 0x80000000u) : ~u;
    return __uint_as_float(b);
}

// Packed fp32x2 FMA (Blackwell FFMA2).
__device__ __forceinline__ unsigned long long ffma2(
    unsigned long long a, unsigned long long b, unsigned long long c) {
    unsigned long long d;
    asm("fma.rn.f32x2 %0, %1, %2, %3;" : "=l"(d) : "l"(a), "l"(b), "l"(c));
    return d;
}

// ---------------------------------------------------------------------------
// Kernel A: per-batch prep via histogram select. grid = 32, 256 threads.
// Output: g_scal[b] = {inv_r, Tp, Tn, flag}
//   Tp = inv_h * (sum of top-16 of f_histo[b]) / 16, Tn likewise bottom-16.
// ---------------------------------------------------------------------------
__global__ void __launch_bounds__(256) prep_kernel(
    const float* __restrict__ f_rad,    // [32,1024]
    const float* __restrict__ f_histo,  // [32,2048]
    const int*   __restrict__ rad_mask, // [32]
    const int*   __restrict__ histo_mask)
{
    const int b    = blockIdx.x;
    const int tid  = threadIdx.x;
    const int lane = tid & 31;
    const int wid  = tid >> 5;

    __shared__ unsigned s_hist[2048];   // 11-bit bins
    __shared__ unsigned s_candT[2048];  // boundary-bin candidates (worst case all)
    __shared__ unsigned s_candB[2048];
    __shared__ float    s_red[16];      // warp partial sumsq (rad, histo)
    __shared__ unsigned s_mm[16];       // warp max ord, warp min ord
    __shared__ int      s_bnd[4];       // Btop, cnt_above, Bbot, cnt_below
    __shared__ unsigned s_cnt[2];       // candidate counters
    __shared__ float    s_sum[16];      // warp partial sumAbove, sumBelow
    __shared__ float    s_scal[4];      // inv_r, inv_h, sumTop, sumBot

    const float* rad = f_rad   + b * 1024;
    const float* his = f_histo + b * 2048;

    // --- clear histogram / counters
    #pragma unroll
    for (int j = 0; j < 8; j++) s_hist[tid + 256 * j] = 0;
    if (tid < 2) s_cnt[tid] = 0;

    // --- load, sum-of-squares, ord-map, min/max
    float sr = 0.f, sh = 0.f;
    unsigned v8[8], mx = 0u, mn = 0xFFFFFFFFu;
    #pragma unroll
    for (int j = 0; j < 4; j++) { float x = rad[tid + 256 * j]; sr += x * x; }
    #pragma unroll
    for (int j = 0; j < 8; j++) {
        float x = his[tid + 256 * j];
        sh += x * x;
        unsigned o = f2ord(x);
        v8[j] = o; mx = max(mx, o); mn = min(mn, o);
    }
    #pragma unroll
    for (int o = 16; o > 0; o >>= 1) {
        sr += __shfl_xor_sync(FULL, sr, o);
        sh += __shfl_xor_sync(FULL, sh, o);
    }
    mx = __reduce_max_sync(FULL, mx);
    mn = __reduce_min_sync(FULL, mn);
    if (lane == 0) { s_red[wid] = sr; s_red[8 + wid] = sh; s_mm[wid] = mx; s_mm[8 + wid] = mn; }
    __syncthreads();   // hist cleared + warp partials visible

    // --- histogram (atomics on spread bins)
    #pragma unroll
    for (int j = 0; j < 8; j++) atomicAdd(&s_hist[v8[j] >> 21], 1u);

    if (tid == 0) {
        float a = 0.f, c2 = 0.f;
        unsigned MX = 0u, MN = 0xFFFFFFFFu;
        #pragma unroll
        for (int w = 0; w < 8; w++) {
            a += s_red[w]; c2 += s_red[8 + w];
            MX = max(MX, s_mm[w]); MN = min(MN, s_mm[8 + w]);
        }
        s_scal[0] = 1.f / fmaxf(sqrtf(a),  1e-12f);
        s_scal[1] = 1.f / fmaxf(sqrtf(c2), 1e-12f);
        s_mm[0] = MX; s_mm[8] = MN;
    }
    __syncthreads();   // histogram complete, global max/min ready

    // --- boundary search: warp 0 downward from max bin, warp 1 upward from min
    if (wid == 0) {
        int bin = (int)(s_mm[0] >> 21);
        unsigned cum = 0;
        while (true) {
            int ib = bin - lane;
            unsigned c = (ib >= 0) ? s_hist[ib] : 0u;
            unsigned p = c;
            #pragma unroll
            for (int o = 1; o < 32; o <<= 1) {
                unsigned t = __shfl_up_sync(FULL, p, o);
                if (lane >= o) p += t;
            }
            unsigned ball = __ballot_sync(FULL, cum + p >= 16u);
            if (ball) {
                int l = __ffs(ball) - 1;
                unsigned pl = __shfl_sync(FULL, p, l);
                unsigned cl = __shfl_sync(FULL, c, l);
                if (lane == 0) { s_bnd[0] = bin - l; s_bnd[1] = (int)(cum + pl - cl); }
                break;
            }
            cum += __shfl_sync(FULL, p, 31);
            bin -= 32;
        }
    } else if (wid == 1) {
        int bin = (int)(s_mm[8] >> 21);
        unsigned cum = 0;
        while (true) {
            int ib = bin + lane;
            unsigned c = (ib < 2048) ? s_hist[ib] : 0u;
            unsigned p = c;
            #pragma unroll
            for (int o = 1; o < 32; o <<= 1) {
                unsigned t = __shfl_up_sync(FULL, p, o);
                if (lane >= o) p += t;
            }
            unsigned ball = __ballot_sync(FULL, cum + p >= 16u);
            if (ball) {
                int l = __ffs(ball) - 1;
                unsigned pl = __shfl_sync(FULL, p, l);
                unsigned cl = __shfl_sync(FULL, c, l);
                if (lane == 0) { s_bnd[2] = bin + l; s_bnd[3] = (int)(cum + pl - cl); }
                break;
            }
            cum += __shfl_sync(FULL, p, 31);
            bin += 32;
        }
    }
    __syncthreads();

    const int Btop = s_bnd[0];
    const int Bbot = s_bnd[2];

    // --- parallel: sum strictly beyond boundary bins + collect boundary cands
    float sA = 0.f, sB = 0.f;
    #pragma unroll
    for (int j = 0; j < 8; j++) {
        unsigned o = v8[j];
        int bn = (int)(o >> 21);
        if (bn > Btop)       sA += ord2f(o);
        else if (bn == Btop) { unsigned p = atomicAdd(&s_cnt[0], 1u); s_candT[p] = o; }
        if (bn < Bbot)       sB += ord2f(o);
        else if (bn == Bbot) { unsigned p = atomicAdd(&s_cnt[1], 1u); s_candB[p] = o; }
    }
    #pragma unroll
    for (int o = 16; o > 0; o >>= 1) {
        sA += __shfl_xor_sync(FULL, sA, o);
        sB += __shfl_xor_sync(FULL, sB, o);
    }
    if (lane == 0) { s_sum[wid] = sA; s_sum[8 + wid] = sB; }
    __syncthreads();

    // --- boundary extraction (tiny lists, m passes)
    if (wid == 0) {
        float sum = 0.f;
        #pragma unroll
        for (int w = 0; w < 8; w++) sum += s_sum[w];
        const int m = 16 - s_bnd[1];
        const int cnt = (int)s_cnt[0];
        for (int pass = 0; pass < m; pass++) {
            unsigned best = 0u;
            for (int i = lane; i < cnt; i += 32) best = max(best, s_candT[i]);
            unsigned wm = __reduce_max_sync(FULL, best);
            sum += ord2f(wm);
            int idx = -1;
            for (int i = lane; i < cnt; i += 32)
                if (s_candT[i] == wm) { idx = i; break; }
            unsigned ball = __ballot_sync(FULL, idx >= 0);
            if (lane == (int)__ffs(ball) - 1) s_candT[idx] = 0u;
        }
        if (lane == 0) s_scal[2] = sum;
    } else if (wid == 1) {
        float sum = 0.f;
        #pragma unroll
        for (int w = 0; w < 8; w++) sum += s_sum[8 + w];
        const int m = 16 - s_bnd[3];
        const int cnt = (int)s_cnt[1];
        for (int pass = 0; pass < m; pass++) {
            unsigned best = 0xFFFFFFFFu;
            for (int i = lane; i < cnt; i += 32) best = min(best, s_candB[i]);
            unsigned wm = __reduce_min_sync(FULL, best);
            sum += ord2f(wm);
            int idx = -1;
            for (int i = lane; i < cnt; i += 32)
                if (s_candB[i] == wm) { idx = i; break; }
            unsigned ball = __ballot_sync(FULL, idx >= 0);
            if (lane == (int)__ffs(ball) - 1) s_candB[idx] = 0xFFFFFFFFu;
        }
        if (lane == 0) s_scal[3] = sum;
    }
    __syncthreads();

    if (tid == 0) {
        float flag = ((rad_mask[b] != 0) && (histo_mask[b] != 0)) ? 0.f : 1.f;
        float Tp = s_scal[1] * s_scal[2] * (1.f / 16.f);
        float Tn = s_scal[1] * s_scal[3] * (1.f / 16.f);
        g_scal[b] = make_float4(s_scal[0], Tp, Tn, flag);
    }
}

// ---------------------------------------------------------------------------
// Kernel B: split-K GEMM, atomic-free (unchanged from R5).
// ---------------------------------------------------------------------------
__global__ void __launch_bounds__(256) gemm_kernel(
    const float* __restrict__ W,      // [1024, 2048]
    const float* __restrict__ f_rad)  // [32, 1024]
{
    const int c0    = blockIdx.x * 64;
    const int split = blockIdx.y;
    const int k0    = split * 64;
    const int tid   = threadIdx.x;
    const int lane  = tid & 31;
    const int wid   = tid >> 5;

    __shared__ __align__(16) float  Ws[64 * 64];   // [c][k] 16KB
    __shared__ __align__(16) float  Fs[32 * 68];   // [b][k] pitch 68
    __shared__ float4 s_sc[32];

    const float4* W4 = (const float4*)W;
    const int kq  = tid & 15;
    const int cl  = tid >> 4;
    const int kq0 = k0 >> 2;
    float4 wv[4];
    #pragma unroll
    for (int j = 0; j < 4; j++)
        wv[j] = W4[(size_t)(c0 + cl + 16 * j) * 512 + kq0 + kq];

    const float4* R4 = (const float4*)f_rad;
    const int kb = (k0 & 1023) >> 2;
    float4 rv[2];
    #pragma unroll
    for (int j = 0; j < 2; j++) {
        int i = tid + 256 * j;
        rv[j] = R4[(size_t)(i >> 4) * 256 + kb + (i & 15)];
    }
    if (tid < 32) s_sc[tid] = g_scal[tid];
    __syncthreads();

    const bool neg = (k0 >= 1024);
    #pragma unroll
    for (int j = 0; j < 2; j++) {
        int i  = tid + 256 * j;
        int bb = i >> 4;
        float4 sc = s_sc[bb];
        float ca = (neg ? -sc.z : sc.y) * sc.x;
        float cb = (neg ? -sc.y : sc.z) * sc.x;
        float4 r = rv[j], f;
        f.x = ca * fmaxf(r.x, 0.f) + cb * fminf(r.x, 0.f);
        f.y = ca * fmaxf(r.y, 0.f) + cb * fminf(r.y, 0.f);
        f.z = ca * fmaxf(r.z, 0.f) + cb * fminf(r.z, 0.f);
        f.w = ca * fmaxf(r.w, 0.f) + cb * fminf(r.w, 0.f);
        *(float4*)&Fs[bb * 68 + 4 * (i & 15)] = f;
    }
    #pragma unroll
    for (int j = 0; j < 4; j++)
        *(float4*)&Ws[(cl + 16 * j) * 64 + 4 * kq] = wv[j];
    __syncthreads();

    const int cw = wid * 8;
    const ulonglong2* wrow = (const ulonglong2*)&Ws[cw * 64];
    const ulonglong2* frow = (const ulonglong2*)&Fs[lane * 68];

    unsigned long long acc[8];
    #pragma unroll
    for (int c = 0; c < 8; c++) acc[c] = 0ull;

    #pragma unroll
    for (int ki = 0; ki < 16; ki++) {
        ulonglong2 f = frow[ki];
        #pragma unroll
        for (int c = 0; c < 8; c++) {
            ulonglong2 w = wrow[c * 16 + ki];
            acc[c] = ffma2(w.x, f.x, acc[c]);
            acc[c] = ffma2(w.y, f.y, acc[c]);
        }
    }

    float o8[8];
    #pragma unroll
    for (int c = 0; c < 8; c++) {
        float lo = __uint_as_float((unsigned)(acc[c] & 0xffffffffull));
        float hi = __uint_as_float((unsigned)(acc[c] >> 32));
        o8[c] = lo + hi;
    }
    float* dst = &g_part[((size_t)split * 32 + lane) * 1024 + c0 + cw];
    *(float4*)(dst + 0) = make_float4(o8[0], o8[1], o8[2], o8[3]);
    *(float4*)(dst + 4) = make_float4(o8[4], o8[5], o8[6], o8[7]);
}

// ---------------------------------------------------------------------------
// Kernel C: reduce split partials + bias + flag*token -> out (unchanged).
// ---------------------------------------------------------------------------
__device__ __forceinline__ float4 f4add(float4 a, float4 b) {
    return make_float4(a.x + b.x, a.y + b.y, a.z + b.z, a.w + b.w);
}

__global__ void __launch_bounds__(256) reduce_kernel(
    const float* __restrict__ bias,   // [1024]
    const float* __restrict__ token,  // [1024]
    float* __restrict__ out)          // [32,1024]
{
    const int b   = blockIdx.x;
    const int tid = threadIdx.x;

    const float4* P4 = (const float4*)g_part;
    const size_t base   = (size_t)b * 256 + tid;
    const size_t stride = 32 * 256;

    float4 a0 = make_float4(0, 0, 0, 0), a1 = a0, a2 = a0, a3 = a0;
    #pragma unroll
    for (int s = 0; s < 32; s += 4) {
        a0 = f4add(a0, P4[base + (size_t)(s + 0) * stride]);
        a1 = f4add(a1, P4[base + (size_t)(s + 1) * stride]);
        a2 = f4add(a2, P4[base + (size_t)(s + 2) * stride]);
        a3 = f4add(a3, P4[base + (size_t)(s + 3) * stride]);
    }
    float4 acc = f4add(f4add(a0, a1), f4add(a2, a3));

    const float flag = g_scal[b].w;
    float4 bs = ((const float4*)bias)[tid];
    float4 tk = ((const float4*)token)[tid];
    float4 o;
    o.x = acc.x + bs.x + flag * tk.x;
    o.y = acc.y + bs.y + flag * tk.y;
    o.z = acc.z + bs.z + flag * tk.z;
    o.w = acc.w + bs.w + flag * tk.w;
    ((float4*)out)[(size_t)b * 256 + tid] = o;
}

extern "C" void kernel_launch(void* const* d_in, const int* in_sizes, int n_in,
                              void* d_out, int out_size) {
    const float* f_rad      = (const float*)d_in[0];
    const float* f_histo    = (const float*)d_in[1];
    const int*   rad_mask   = (const int*)  d_in[2];
    const int*   histo_mask = (const int*)  d_in[3];
    const float* W          = (const float*)d_in[4];
    const float* bias       = (const float*)d_in[5];
    const float* token      = (const float*)d_in[6];
    float* out = (float*)d_out;

    prep_kernel<<<32, 256>>>(f_rad, f_histo, rad_mask, histo_mask);
    gemm_kernel<<<dim3(16, 32), 256>>>(W, f_rad);
    reduce_kernel<<<32, 256>>>(bias, token, out);
}

// round 7
// speedup vs baseline: 1.5306x; 1.0889x over previous
#include <cuda_runtime.h>
#include <cstdint>

#define FULL 0xFFFFFFFFu

// Static scratch (no allocations):
__device__ float4 g_scal[32];                 // per-b: {inv_r, Tp, Tn, flag}
__device__ float  g_part[2 * 32 * 32 * 1024]; // [arr(p/m)][split][b][c], 8MB

// Order-preserving float <-> uint mapping (monotone for non-NaN).
__device__ __forceinline__ unsigned f2ord(float f) {
    unsigned b = __float_as_uint(f);
    return (b & 0x80000000u) ? ~b : (b | 0x80000000u);
}
__device__ __forceinline__ float ord2f(unsigned u) {
    unsigned b = (u & 0x80000000u) ? (u ^ 0x80000000u) : ~u;
    return __uint_as_float(b);
}

// Packed fp32x2 FMA (Blackwell FFMA2).
__device__ __forceinline__ unsigned long long ffma2(
    unsigned long long a, unsigned long long b, unsigned long long c) {
    unsigned long long d;
    asm("fma.rn.f32x2 %0, %1, %2, %3;" : "=l"(d) : "l"(a), "l"(b), "l"(c));
    return d;
}

// ---------------------------------------------------------------------------
// Fused kernel: blocks 0..31 = prep (per-batch scalars via histogram select),
// blocks 32..543 = scalar-free split-K GEMM partials. NO inter-block deps.
// ---------------------------------------------------------------------------
union SmemU {
    struct {
        unsigned hist[2048];
        unsigned candT[2048];
        unsigned candB[2048];
        float    red[16];
        unsigned mm[16];
        int      bnd[4];
        unsigned cnt[2];
        float    sum[16];
        float    scal[4];
    } p;
    struct {
        float Ws[64 * 64];      // [c][k] 16KB
        float FsP[32 * 68];     // max(rad,0), pitch 68
        float FsM[32 * 68];     // min(rad,0)
    } g;
};

__global__ void __launch_bounds__(256) fused_kernel(
    const float* __restrict__ f_rad,    // [32,1024]
    const float* __restrict__ f_histo,  // [32,2048]
    const int*   __restrict__ rad_mask, // [32]
    const int*   __restrict__ histo_mask,
    const float* __restrict__ W)        // [1024,2048]
{
    __shared__ __align__(16) SmemU sm;

    const int tid  = threadIdx.x;
    const int lane = tid & 31;
    const int wid  = tid >> 5;

    if (blockIdx.x < 32) {
        // ======================= PREP =======================
        const int b = blockIdx.x;
        const float* rad = f_rad   + b * 1024;
        const float* his = f_histo + b * 2048;

        #pragma unroll
        for (int j = 0; j < 8; j++) sm.p.hist[tid + 256 * j] = 0;
        if (tid < 2) sm.p.cnt[tid] = 0;

        float sr = 0.f, sh = 0.f;
        unsigned v8[8], mx = 0u, mn = 0xFFFFFFFFu;
        #pragma unroll
        for (int j = 0; j < 4; j++) { float x = rad[tid + 256 * j]; sr += x * x; }
        #pragma unroll
        for (int j = 0; j < 8; j++) {
            float x = his[tid + 256 * j];
            sh += x * x;
            unsigned o = f2ord(x);
            v8[j] = o; mx = max(mx, o); mn = min(mn, o);
        }
        #pragma unroll
        for (int o = 16; o > 0; o >>= 1) {
            sr += __shfl_xor_sync(FULL, sr, o);
            sh += __shfl_xor_sync(FULL, sh, o);
        }
        mx = __reduce_max_sync(FULL, mx);
        mn = __reduce_min_sync(FULL, mn);
        if (lane == 0) { sm.p.red[wid] = sr; sm.p.red[8 + wid] = sh; sm.p.mm[wid] = mx; sm.p.mm[8 + wid] = mn; }
        __syncthreads();

        #pragma unroll
        for (int j = 0; j < 8; j++) atomicAdd(&sm.p.hist[v8[j] >> 21], 1u);

        if (tid == 0) {
            float a = 0.f, c2 = 0.f;
            unsigned MX = 0u, MN = 0xFFFFFFFFu;
            #pragma unroll
            for (int w = 0; w < 8; w++) {
                a += sm.p.red[w]; c2 += sm.p.red[8 + w];
                MX = max(MX, sm.p.mm[w]); MN = min(MN, sm.p.mm[8 + w]);
            }
            sm.p.scal[0] = 1.f / fmaxf(sqrtf(a),  1e-12f);
            sm.p.scal[1] = 1.f / fmaxf(sqrtf(c2), 1e-12f);
            sm.p.mm[0] = MX; sm.p.mm[8] = MN;
        }
        __syncthreads();

        if (wid == 0) {
            int bin = (int)(sm.p.mm[0] >> 21);
            unsigned cum = 0;
            while (true) {
                int ib = bin - lane;
                unsigned c = (ib >= 0) ? sm.p.hist[ib] : 0u;
                unsigned p = c;
                #pragma unroll
                for (int o = 1; o < 32; o <<= 1) {
                    unsigned t = __shfl_up_sync(FULL, p, o);
                    if (lane >= o) p += t;
                }
                unsigned ball = __ballot_sync(FULL, cum + p >= 16u);
                if (ball) {
                    int l = __ffs(ball) - 1;
                    unsigned pl = __shfl_sync(FULL, p, l);
                    unsigned cl = __shfl_sync(FULL, c, l);
                    if (lane == 0) { sm.p.bnd[0] = bin - l; sm.p.bnd[1] = (int)(cum + pl - cl); }
                    break;
                }
                cum += __shfl_sync(FULL, p, 31);
                bin -= 32;
            }
        } else if (wid == 1) {
            int bin = (int)(sm.p.mm[8] >> 21);
            unsigned cum = 0;
            while (true) {
                int ib = bin + lane;
                unsigned c = (ib < 2048) ? sm.p.hist[ib] : 0u;
                unsigned p = c;
                #pragma unroll
                for (int o = 1; o < 32; o <<= 1) {
                    unsigned t = __shfl_up_sync(FULL, p, o);
                    if (lane >= o) p += t;
                }
                unsigned ball = __ballot_sync(FULL, cum + p >= 16u);
                if (ball) {
                    int l = __ffs(ball) - 1;
                    unsigned pl = __shfl_sync(FULL, p, l);
                    unsigned cl = __shfl_sync(FULL, c, l);
                    if (lane == 0) { sm.p.bnd[2] = bin + l; sm.p.bnd[3] = (int)(cum + pl - cl); }
                    break;
                }
                cum += __shfl_sync(FULL, p, 31);
                bin += 32;
            }
        }
        __syncthreads();

        const int Btop = sm.p.bnd[0];
        const int Bbot = sm.p.bnd[2];

        float sA = 0.f, sB = 0.f;
        #pragma unroll
        for (int j = 0; j < 8; j++) {
            unsigned o = v8[j];
            int bn = (int)(o >> 21);
            if (bn > Btop)       sA += ord2f(o);
            else if (bn == Btop) { unsigned p = atomicAdd(&sm.p.cnt[0], 1u); sm.p.candT[p] = o; }
            if (bn < Bbot)       sB += ord2f(o);
            else if (bn == Bbot) { unsigned p = atomicAdd(&sm.p.cnt[1], 1u); sm.p.candB[p] = o; }
        }
        #pragma unroll
        for (int o = 16; o > 0; o >>= 1) {
            sA += __shfl_xor_sync(FULL, sA, o);
            sB += __shfl_xor_sync(FULL, sB, o);
        }
        if (lane == 0) { sm.p.sum[wid] = sA; sm.p.sum[8 + wid] = sB; }
        __syncthreads();

        if (wid == 0) {
            float sum = 0.f;
            #pragma unroll
            for (int w = 0; w < 8; w++) sum += sm.p.sum[w];
            const int m = 16 - sm.p.bnd[1];
            const int cnt = (int)sm.p.cnt[0];
            for (int pass = 0; pass < m; pass++) {
                unsigned best = 0u;
                for (int i = lane; i < cnt; i += 32) best = max(best, sm.p.candT[i]);
                unsigned wm = __reduce_max_sync(FULL, best);
                sum += ord2f(wm);
                int idx = -1;
                for (int i = lane; i < cnt; i += 32)
                    if (sm.p.candT[i] == wm) { idx = i; break; }
                unsigned ball = __ballot_sync(FULL, idx >= 0);
                if (lane == (int)__ffs(ball) - 1) sm.p.candT[idx] = 0u;
            }
            if (lane == 0) sm.p.scal[2] = sum;
        } else if (wid == 1) {
            float sum = 0.f;
            #pragma unroll
            for (int w = 0; w < 8; w++) sum += sm.p.sum[8 + w];
            const int m = 16 - sm.p.bnd[3];
            const int cnt = (int)sm.p.cnt[1];
            for (int pass = 0; pass < m; pass++) {
                unsigned best = 0xFFFFFFFFu;
                for (int i = lane; i < cnt; i += 32) best = min(best, sm.p.candB[i]);
                unsigned wm = __reduce_min_sync(FULL, best);
                sum += ord2f(wm);
                int idx = -1;
                for (int i = lane; i < cnt; i += 32)
                    if (sm.p.candB[i] == wm) { idx = i; break; }
                unsigned ball = __ballot_sync(FULL, idx >= 0);
                if (lane == (int)__ffs(ball) - 1) sm.p.candB[idx] = 0xFFFFFFFFu;
            }
            if (lane == 0) sm.p.scal[3] = sum;
        }
        __syncthreads();

        if (tid == 0) {
            float flag = ((rad_mask[b] != 0) && (histo_mask[b] != 0)) ? 0.f : 1.f;
            float Tp = sm.p.scal[1] * sm.p.scal[2] * (1.f / 16.f);
            float Tn = sm.p.scal[1] * sm.p.scal[3] * (1.f / 16.f);
            g_scal[b] = make_float4(sm.p.scal[0], Tp, Tn, flag);
        }
    } else {
        // ======================= GEMM (scalar-free partials) =======================
        const int gb    = blockIdx.x - 32;
        const int c0    = (gb & 15) * 64;
        const int split = gb >> 4;
        const int k0    = split * 64;

        // ---- batched prefetch: 4x W LDG.128 + 2x rad LDG.128
        const float4* W4 = (const float4*)W;
        const int kq  = tid & 15;
        const int cl  = tid >> 4;
        const int kq0 = k0 >> 2;
        float4 wv[4];
        #pragma unroll
        for (int j = 0; j < 4; j++)
            wv[j] = W4[(size_t)(c0 + cl + 16 * j) * 512 + kq0 + kq];

        const float4* R4 = (const float4*)f_rad;
        const int kb = (k0 & 1023) >> 2;    // rad column base (k mod 1024)
        float4 rv[2];
        #pragma unroll
        for (int j = 0; j < 2; j++) {
            int i = tid + 256 * j;
            rv[j] = R4[(size_t)(i >> 4) * 256 + kb + (i & 15)];
        }

        // ---- stores: split rad into p = max(r,0), m = min(r,0)
        #pragma unroll
        for (int j = 0; j < 2; j++) {
            int i  = tid + 256 * j;
            int bb = i >> 4;
            float4 r = rv[j], p, m;
            p.x = fmaxf(r.x, 0.f); m.x = fminf(r.x, 0.f);
            p.y = fmaxf(r.y, 0.f); m.y = fminf(r.y, 0.f);
            p.z = fmaxf(r.z, 0.f); m.z = fminf(r.z, 0.f);
            p.w = fmaxf(r.w, 0.f); m.w = fminf(r.w, 0.f);
            *(float4*)&sm.g.FsP[bb * 68 + 4 * (i & 15)] = p;
            *(float4*)&sm.g.FsM[bb * 68 + 4 * (i & 15)] = m;
        }
        #pragma unroll
        for (int j = 0; j < 4; j++)
            *(float4*)&sm.g.Ws[(cl + 16 * j) * 64 + 4 * kq] = wv[j];
        __syncthreads();

        // ---- microkernel: warp owns 8 c rows, lane = b; dual accumulators
        const int cw = wid * 8;
        const ulonglong2* wrow = (const ulonglong2*)&sm.g.Ws[cw * 64];
        const ulonglong2* fp   = (const ulonglong2*)&sm.g.FsP[lane * 68];
        const ulonglong2* fm   = (const ulonglong2*)&sm.g.FsM[lane * 68];

        unsigned long long accp[8], accm[8];
        #pragma unroll
        for (int c = 0; c < 8; c++) { accp[c] = 0ull; accm[c] = 0ull; }

        #pragma unroll
        for (int ki = 0; ki < 16; ki++) {
            ulonglong2 fpv = fp[ki];
            ulonglong2 fmv = fm[ki];
            #pragma unroll
            for (int c = 0; c < 8; c++) {
                ulonglong2 w = wrow[c * 16 + ki];   // reused for both accs
                accp[c] = ffma2(w.x, fpv.x, accp[c]);
                accp[c] = ffma2(w.y, fpv.y, accp[c]);
                accm[c] = ffma2(w.x, fmv.x, accm[c]);
                accm[c] = ffma2(w.y, fmv.y, accm[c]);
            }
        }

        // ---- fold + plain stores
        float op[8], om[8];
        #pragma unroll
        for (int c = 0; c < 8; c++) {
            op[c] = __uint_as_float((unsigned)(accp[c] & 0xffffffffull))
                  + __uint_as_float((unsigned)(accp[c] >> 32));
            om[c] = __uint_as_float((unsigned)(accm[c] & 0xffffffffull))
                  + __uint_as_float((unsigned)(accm[c] >> 32));
        }
        float* dp = &g_part[(((size_t)0 * 32 + split) * 32 + lane) * 1024 + c0 + cw];
        float* dm = &g_part[(((size_t)1 * 32 + split) * 32 + lane) * 1024 + c0 + cw];
        *(float4*)(dp + 0) = make_float4(op[0], op[1], op[2], op[3]);
        *(float4*)(dp + 4) = make_float4(op[4], op[5], op[6], op[7]);
        *(float4*)(dm + 0) = make_float4(om[0], om[1], om[2], om[3]);
        *(float4*)(dm + 4) = make_float4(om[4], om[5], om[6], om[7]);
    }
}

// ---------------------------------------------------------------------------
// Reduce: out[b,c] = bias + flag*token
//   + Σ_{s<16}  ( Tp*inv_r*Pp + Tn*inv_r*Pm )
//   + Σ_{s>=16} (-Tn*inv_r*Pp - Tp*inv_r*Pm )
// grid = 32 (b), 256 threads (c float4s).
// ---------------------------------------------------------------------------
__device__ __forceinline__ float4 f4add(float4 a, float4 b) {
    return make_float4(a.x + b.x, a.y + b.y, a.z + b.z, a.w + b.w);
}

__global__ void __launch_bounds__(256) reduce_kernel(
    const float* __restrict__ bias,   // [1024]
    const float* __restrict__ token,  // [1024]
    float* __restrict__ out)          // [32,1024]
{
    const int b   = blockIdx.x;
    const int tid = threadIdx.x;

    const float4* P4 = (const float4*)g_part;
    const size_t base   = (size_t)b * 256 + tid;   // float4 idx at [arr=0][s=0]
    const size_t sstr   = 32 * 256;                // split stride (float4s)
    const size_t astr   = 32 * sstr;               // array stride

    float4 z = make_float4(0, 0, 0, 0);
    float4 P1 = z, P2 = z, M1 = z, M2 = z;
    #pragma unroll
    for (int s = 0; s < 16; s++) {
        P1 = f4add(P1, P4[base + (size_t)s * sstr]);
        P2 = f4add(P2, P4[base + (size_t)(s + 16) * sstr]);
        M1 = f4add(M1, P4[base + astr + (size_t)s * sstr]);
        M2 = f4add(M2, P4[base + astr + (size_t)(s + 16) * sstr]);
    }

    float4 sc = g_scal[b];
    const float cp = sc.x * sc.y;   // inv_r * Tp
    const float cn = sc.x * sc.z;   // inv_r * Tn
    const float flag = sc.w;

    float4 bs = ((const float4*)bias)[tid];
    float4 tk = ((const float4*)token)[tid];
    float4 o;
    o.x = bs.x + flag * tk.x + cp * (P1.x - M2.x) + cn * (M1.x - P2.x);
    o.y = bs.y + flag * tk.y + cp * (P1.y - M2.y) + cn * (M1.y - P2.y);
    o.z = bs.z + flag * tk.z + cp * (P1.z - M2.z) + cn * (M1.z - P2.z);
    o.w = bs.w + flag * tk.w + cp * (P1.w - M2.w) + cn * (M1.w - P2.w);
    ((float4*)out)[(size_t)b * 256 + tid] = o;
}

extern "C" void kernel_launch(void* const* d_in, const int* in_sizes, int n_in,
                              void* d_out, int out_size) {
    const float* f_rad      = (const float*)d_in[0];
    const float* f_histo    = (const float*)d_in[1];
    const int*   rad_mask   = (const int*)  d_in[2];
    const int*   histo_mask = (const int*)  d_in[3];
    const float* W          = (const float*)d_in[4];
    const float* bias       = (const float*)d_in[5];
    const float* token      = (const float*)d_in[6];
    float* out = (float*)d_out;

    fused_kernel<<<544, 256>>>(f_rad, f_histo, rad_mask, histo_mask, W);
    reduce_kernel<<<32, 256>>>(bias, token, out);
}